// round 13
// baseline (speedup 1.0000x reference)
#include <cuda_runtime.h>
#include <cstdint>
#include <cuda_fp16.h>

// ============================================================================
// out[b,n] = sum_k x[b,k] * W[k,n]
//   x: [512, 2^20] f32, W: [2^20, 128] f32, out: [512,128] f32
// R7 design (fused, no prepass):
//   K1: GEMM, CTA 128x128, KTILE=32, split-K 74 (grid 296 = 148 SMs x occ 2).
//       4 warps (2m x 2n), warp tile 64x64.
//       A: coalesced LDG f32 -> reg -> F2FP pack -> STS fp16 (double buffer)
//       B: coalesced LDG f32 (row-pairs) -> reg -> pair-pack fp16 -> STS
//          (double buffer). W converted on the fly; L2 dedups the 4-way
//          mt redundancy. ONE __syncthreads per stage.
//       mma.sync.m16n8k16.f16 with f32 accumulators. Tensor-pipe-bound
//       (legacy HMMA = 512 MAC/cyc/SM on sm_103).
//   K2: reduce split-K partials
// ============================================================================

static constexpr int M_TOTAL = 512;
static constexpr int N_DIM   = 128;
static constexpr int K_TOTAL = 1 << 20;

static constexpr int MTILE   = 128;
static constexpr int KTILE   = 32;
static constexpr int NUM_MT  = M_TOTAL / MTILE;    // 4
static constexpr int KSPLITS = 74;                 // 296 CTAs = one wave @ occ 2
static constexpr int NTILES_K = K_TOTAL / KTILE;   // 32768
static constexpr int BASE_T  = NTILES_K / KSPLITS; // 442
static constexpr int REM_T   = NTILES_K - BASE_T * KSPLITS; // 60

// smem (u32 units)
static constexpr int AH_PITCH = 20;                     // 16 data u32 + 4 pad
static constexpr int AH_WORDS = MTILE * AH_PITCH;       // 2560 (one buffer)
static constexpr int BH_PITCH = 136;                    // 128 data + 8 pad
static constexpr int BH_SLOT  = (KTILE / 2) * BH_PITCH; // 2176 (one buffer)
static constexpr int SMEM_WORDS = 2 * AH_WORDS + 2 * BH_SLOT; // 9472
static constexpr int SMEM_BYTES = SMEM_WORDS * 4;             // 37888

// split-K partials scratch
__device__ float g_part[(size_t)KSPLITS * NUM_MT * MTILE * N_DIM]; // 19.4 MiB

// ---------------------------------------------------------------------------
__device__ __forceinline__ uint32_t pack_h2(float lo, float hi) {
    __half2 h = __floats2half2_rn(lo, hi);   // .x = lo (low 16 bits)
    return *reinterpret_cast<uint32_t*>(&h);
}
__device__ __forceinline__ void mma_f16(float* d, const uint32_t* a, const uint32_t* b) {
    asm volatile(
        "mma.sync.aligned.m16n8k16.row.col.f32.f16.f16.f32 "
        "{%0,%1,%2,%3}, {%4,%5,%6,%7}, {%8,%9}, {%0,%1,%2,%3};"
        : "+f"(d[0]), "+f"(d[1]), "+f"(d[2]), "+f"(d[3])
        : "r"(a[0]), "r"(a[1]), "r"(a[2]), "r"(a[3]), "r"(b[0]), "r"(b[1]));
}

// ---------------------------------------------------------------------------
// K1: GEMM. grid 296 (mt = bid&3, ks = bid>>2), 128 threads,
// 4 warps as 2(m) x 2(n), warp tile 64x64.
// ---------------------------------------------------------------------------
__global__ void __launch_bounds__(128, 2) gemm_kernel(
    const float* __restrict__ x, const float* __restrict__ W,
    float* __restrict__ partials) {
    extern __shared__ uint32_t smem[];
    uint32_t* const sAh = smem;                     // 2 x [128][20]
    uint32_t* const sBh = smem + 2 * AH_WORDS;      // 2 x [16][136]

    const int tid  = threadIdx.x;
    const int wid  = tid >> 5;
    const int lane = tid & 31;
    const int g = lane >> 2;
    const int c = lane & 3;
    const int m_off = (wid >> 1) * 64;   // 2 m-warps
    const int n_off = (wid & 1) * 64;    // 2 n-warps

    const int mt = blockIdx.x & (NUM_MT - 1);
    const int ks = blockIdx.x >> 2;
    const size_t m_base = (size_t)mt * MTILE;
    const int nt = BASE_T + (ks < REM_T ? 1 : 0);
    const long t0 = (long)ks * BASE_T + (ks < REM_T ? ks : REM_T);

    // A: 8 lanes per row (coalesced). row = 16*pass + (tid>>3), chunk q = tid&7.
    const int a_r = tid >> 3;            // 0..15
    const int a_q = tid & 7;             // 0..7
    const float* const a_base = x + (m_base + a_r) * (size_t)K_TOTAL + a_q * 4;

    // B: thread handles 4 k2-pairs. id = tid + 128*i: k2 = id>>5 (0..15),
    // nq = id&31. Loads rows 2*k2 and 2*k2+1 at float col nq*4 (coalesced 512B).
    const int b_k2 = tid >> 5;           // 0..3 (plus 4*i)
    const int b_nq = tid & 31;
    const float* const b_base = W + (size_t)b_nq * 4;

    float4 f[8];          // A prefetch regs
    float4 blo[4], bhi[4];// B prefetch regs (4 k2-pairs x 2 rows x 16B)

    auto ld_A = [&](int tile) {
        const float* p = a_base + (size_t)(t0 + tile) * KTILE;
#pragma unroll
        for (int ps = 0; ps < 8; ps++)
            f[ps] = *reinterpret_cast<const float4*>(p + (size_t)ps * 16 * K_TOTAL);
    };
    auto ld_B = [&](int tile) {
        const size_t kg = (size_t)(t0 + tile) * KTILE;
        const float* p = b_base + kg * N_DIM;
#pragma unroll
        for (int i = 0; i < 4; i++) {
            const int k2 = b_k2 + 4 * i;
            blo[i] = *reinterpret_cast<const float4*>(p + (size_t)(2 * k2) * N_DIM);
            bhi[i] = *reinterpret_cast<const float4*>(p + (size_t)(2 * k2 + 1) * N_DIM);
        }
    };

    float acc[4][8][4];   // 4 m16 x 8 n8 tiles = 128 regs
#pragma unroll
    for (int mi = 0; mi < 4; mi++)
#pragma unroll
        for (int ni = 0; ni < 8; ni++)
#pragma unroll
            for (int r = 0; r < 4; r++) acc[mi][ni][r] = 0.0f;

    ld_A(0);
    ld_B(0);

    uint32_t* const a_dst0 = sAh + a_r * AH_PITCH + a_q * 2;
    uint32_t* const b_dst0 = sBh + b_k2 * BH_PITCH + b_nq * 4;

    for (int it = 0; it < nt; it++) {
        const int buf = it & 1;
        // pack A(it) -> Ah[buf]  (STS.64, rows 16*ps + a_r)
        {
            uint32_t* ab = a_dst0 + buf * AH_WORDS;
#pragma unroll
            for (int ps = 0; ps < 8; ps++) {
                uint2 o;
                o.x = pack_h2(f[ps].x, f[ps].y);
                o.y = pack_h2(f[ps].z, f[ps].w);
                *reinterpret_cast<uint2*>(ab + ps * (16 * AH_PITCH)) = o;
            }
        }
        // pack B(it) pairs -> Bh[buf]  (STS.128)
        {
            uint32_t* bb = b_dst0 + buf * BH_SLOT;
#pragma unroll
            for (int i = 0; i < 4; i++) {
                uint4 o;
                o.x = pack_h2(blo[i].x, bhi[i].x);
                o.y = pack_h2(blo[i].y, bhi[i].y);
                o.z = pack_h2(blo[i].z, bhi[i].z);
                o.w = pack_h2(blo[i].w, bhi[i].w);
                *reinterpret_cast<uint4*>(bb + i * (4 * BH_PITCH)) = o;
            }
        }
        if (it + 1 < nt) {     // distance-1 register prefetch (hidden by stage)
            ld_A(it + 1);
            ld_B(it + 1);
        }
        __syncthreads();   // Ah[buf]+Bh[buf] complete; prior reads retired

        const uint32_t* Ahp = sAh + buf * AH_WORDS;
        const uint32_t* Bhp = sBh + buf * BH_SLOT;
#pragma unroll
        for (int kk = 0; kk < 2; kk++) {
            uint32_t a[4][4], b[8][2];
#pragma unroll
            for (int mi = 0; mi < 4; mi++) {
                const int r0 = m_off + mi * 16 + g;
                const uint32_t* A0 = Ahp + r0 * AH_PITCH + kk * 8;
                const uint32_t* A1 = Ahp + (r0 + 8) * AH_PITCH + kk * 8;
                a[mi][0] = A0[c];
                a[mi][1] = A1[c];
                a[mi][2] = A0[c + 4];
                a[mi][3] = A1[c + 4];
            }
#pragma unroll
            for (int ni = 0; ni < 8; ni++) {
                const int col = n_off + ni * 8 + g;
                b[ni][0] = Bhp[(kk * 8 + c) * BH_PITCH + col];
                b[ni][1] = Bhp[(kk * 8 + c + 4) * BH_PITCH + col];
            }
#pragma unroll
            for (int mi = 0; mi < 4; mi++)
#pragma unroll
                for (int ni = 0; ni < 8; ni++)
                    mma_f16(acc[mi][ni], a[mi], b[ni]);
        }
    }

    // epilogue: 128x128 partial
    float* pt = partials + (size_t)blockIdx.x * (MTILE * N_DIM);
#pragma unroll
    for (int mi = 0; mi < 4; mi++) {
        int r0 = m_off + mi * 16 + g;
#pragma unroll
        for (int ni = 0; ni < 8; ni++) {
            int col = n_off + ni * 8 + 2 * c;
            float2 lo = make_float2(acc[mi][ni][0], acc[mi][ni][1]);
            float2 hi = make_float2(acc[mi][ni][2], acc[mi][ni][3]);
            *reinterpret_cast<float2*>(pt + (size_t)r0 * N_DIM + col) = lo;
            *reinterpret_cast<float2*>(pt + (size_t)(r0 + 8) * N_DIM + col) = hi;
        }
    }
}

// ---------------------------------------------------------------------------
// K2: reduce 74 partials -> out, 4-way MLP
// ---------------------------------------------------------------------------
__global__ void __launch_bounds__(256) reduce_kernel(const float* __restrict__ pt,
                                                     float* __restrict__ out) {
    int t = blockIdx.x * blockDim.x + threadIdx.x;
    int n  = t & (N_DIM - 1);
    int m  = (t >> 7) & (MTILE - 1);
    int mt = t >> 14;
    const size_t off = (size_t)m * N_DIM + n;
    const size_t mtoff = (size_t)mt * (MTILE * N_DIM);
    const size_t stride = (size_t)NUM_MT * (MTILE * N_DIM);
    float s0 = 0.f, s1 = 0.f, s2 = 0.f, s3 = 0.f;
    int ks = 0;
#pragma unroll 4
    for (; ks + 4 <= KSPLITS; ks += 4) {
        s0 += pt[(size_t)ks * stride + mtoff + off];
        s1 += pt[(size_t)(ks + 1) * stride + mtoff + off];
        s2 += pt[(size_t)(ks + 2) * stride + mtoff + off];
        s3 += pt[(size_t)(ks + 3) * stride + mtoff + off];
    }
    for (; ks < KSPLITS; ks++) s0 += pt[(size_t)ks * stride + mtoff + off];
    out[(size_t)(mt * MTILE + m) * N_DIM + n] = (s0 + s1) + (s2 + s3);
}

// ---------------------------------------------------------------------------
extern "C" void kernel_launch(void* const* d_in, const int* in_sizes, int n_in,
                              void* d_out, int out_size) {
    const float* x = (const float*)d_in[0];
    const float* W = (const float*)d_in[1];
    float* out = (float*)d_out;

    float* part = nullptr;
    cudaGetSymbolAddress((void**)&part, g_part);

    static bool attr_set = false;
    if (!attr_set) {
        cudaFuncSetAttribute(gemm_kernel, cudaFuncAttributeMaxDynamicSharedMemorySize,
                             SMEM_BYTES);
        attr_set = true;
    }

    gemm_kernel<<<NUM_MT * KSPLITS, 128, SMEM_BYTES>>>(x, W, part);
    reduce_kernel<<<(M_TOTAL * N_DIM) / 256, 256>>>(part, out);
}